// round 11
// baseline (speedup 1.0000x reference)
#include <cuda_runtime.h>
#include <cuda_bf16.h>
#include <math.h>

#define BB   128
#define TT   256
#define SS   64
#define DIN  3
#define HH   512
#define KK   10
#define CSLN 60
#define DOUT 121
#define G4H  2048
#define XD   575   // DIN + CSLN + HH (gemm order: x,win,h)
#define XD1  63    // DIN + CSLN
#define XDP  576   // scan1 permuted+padded: [h 512 | x 3 | win 60 | zero 1]

#define NB   128   // scan blocks (barrier count)
#define NBA  148   // total blocks in fused kernel (all resident)
#define NTS  1024  // threads per scan block (32 warps)

typedef unsigned long long ull;

__device__ __forceinline__ ull pk2(float lo, float hi) {
    ull r; asm("mov.b64 %0,{%1,%2};" : "=l"(r) : "f"(lo), "f"(hi)); return r;
}
__device__ __forceinline__ ull fma2(ull a, ull b, ull c) {
    ull d; asm("fma.rn.f32x2 %0,%1,%2,%3;" : "=l"(d) : "l"(a), "l"(b), "l"(c)); return d;
}
__device__ __forceinline__ ull add2(ull a, ull b) {
    ull d; asm("add.rn.f32x2 %0,%1,%2;" : "=l"(d) : "l"(a), "l"(b)); return d;
}

// ---------------- device scratch ----------------
__device__ __align__(16) float g_h1[BB * HH];
__device__ __align__(16) float g_h1T[2][HH * BB];
__device__ __align__(16) float g_c1T[HH * BB];
__device__ __align__(16) float g_h2T[2][HH * BB];
__device__ __align__(16) float g_c2T[HH * BB];
__device__ __align__(16) float g_p[BB * 3 * KK];
__device__ __align__(16) float g_xw[TT * 64 * BB];   // [t][64: x0..2,win0..59,zero][b]
__device__ __align__(16) float g_h1seqT[TT * HH * BB];
__device__ __align__(16) float g_gates2[TT * G4H * BB];
__device__ __align__(16) float g_yT[TT * HH * BB];
__device__ volatile unsigned g_gen = 0;
__device__ volatile unsigned g_flag[NB * 32];   // padded: one flag per 128B
__device__ unsigned g_ticket = 0;

__device__ __forceinline__ float sigf(float x) { return 1.0f / (1.0f + expf(-x)); }

// flag barrier across the NB scan blocks; target is a monotone generation number
__device__ __forceinline__ void gbar(unsigned target) {
    __syncthreads();
    int tid = threadIdx.x;
    if (blockIdx.x == 0) {
        if (tid == 0) __threadfence();
        if (tid >= 1 && tid < NB) {
            while (g_flag[tid * 32] < target) { }
        }
        __syncthreads();
        if (tid == 0) { __threadfence(); g_gen = target; }
    } else {
        if (tid == 0) {
            __threadfence();
            g_flag[blockIdx.x * 32] = target;
            while (g_gen < target) { }
        }
        __syncthreads();
    }
}

// ---------------- init ----------------
__global__ void init_kernel(const float* __restrict__ x,
                            const float* __restrict__ h1h, const float* __restrict__ h1c,
                            const float* __restrict__ h2h, const float* __restrict__ h2c) {
    int idx = blockIdx.x * blockDim.x + threadIdx.x;
    if (idx == 0) { g_gen = 0; g_ticket = 0; }
    if (idx < NB * 32) g_flag[idx] = 0;
    if (idx < BB * HH) {
        int b = idx / HH, h = idx % HH;
        float v = h1h[idx];
        g_h1[idx] = v;
        g_h1T[0][h * BB + b] = v;
        g_c1T[h * BB + b] = h1c[idx];
        g_h2T[0][h * BB + b] = h2h[idx];
        g_c2T[h * BB + b] = h2c[idx];
    }
    int i2 = idx - BB * HH;
    if (i2 >= 0 && i2 < BB * 3 * KK) g_p[i2] = 0.0f;
    int i3 = idx - BB * HH - BB * 3 * KK;
    if (i3 >= 0 && i3 < TT * DIN * BB) {
        int b = i3 % BB;
        int r = i3 / BB;
        int t = r / DIN, i = r % DIN;
        g_xw[(t * 64 + i) * BB + b] = x[(b * TT + t) * DIN + i];
    }
    int i4 = i3 - TT * DIN * BB;
    if (i4 >= 0 && i4 < TT * BB) {
        int t = i4 / BB, b = i4 % BB;
        g_xw[(t * 64 + 63) * BB + b] = 0.0f;
    }
}

// gemm feature fetch (original order): kg in [0,XD)
__device__ __forceinline__ float fetch_seq(int t, int kg, int bb) {
    if (kg < XD1) return g_xw[(t * 64 + kg) * BB + bb];
    else          return g_h1seqT[(t * HH + (kg - XD1)) * BB + bb];
}

// ---------------- gemm work unit: gates2[t] rows [rt*128, rt*128+128), 1024 thr ----------------
__device__ void gemm_unit(int t, int rt, int tid, char* smraw,
                          const float* __restrict__ W, const float* __restrict__ bias) {
    ull*   a_s = (ull*)smraw;               // [128][33] pairs {w,w}
    float* x_s = (float*)(a_s + 128 * 33);  // [32][128]
    int ty = tid >> 5, tx = tid & 31;       // 32 row-groups of 4, 4 batches each

    ull acc[4][2];
    #pragma unroll
    for (int i = 0; i < 4; i++) { acc[i][0] = 0ull; acc[i][1] = 0ull; }

    for (int k0 = 0; k0 < XD; k0 += 32) {
        for (int i = tid; i < 128 * 32; i += NTS) {
            int row = i >> 5, kk = i & 31;
            int k = k0 + kk;
            float w = (k < XD) ? W[(rt * 128 + row) * XD + k] : 0.0f;
            a_s[row * 33 + kk] = pk2(w, w);
        }
        for (int i = tid; i < 32 * 128; i += NTS) {
            int kk = i >> 7, bb = i & 127;
            int k = k0 + kk;
            x_s[i] = (k < XD) ? fetch_seq(t, k, bb) : 0.0f;
        }
        __syncthreads();
        #pragma unroll 4
        for (int kk = 0; kk < 32; kk++) {
            ulonglong2 xv = *(const ulonglong2*)&x_s[kk * 128 + tx * 4];
            #pragma unroll
            for (int i = 0; i < 4; i++) {
                ull w2 = a_s[(ty * 4 + i) * 33 + kk];
                acc[i][0] = fma2(w2, xv.x, acc[i][0]);
                acc[i][1] = fma2(w2, xv.y, acc[i][1]);
            }
        }
        __syncthreads();
    }
    #pragma unroll
    for (int i = 0; i < 4; i++) {
        int row = rt * 128 + ty * 4 + i;
        float bi = bias[row];
        ull bpr = pk2(bi, bi);
        ull* gp = (ull*)&g_gates2[(size_t)(t * G4H + row) * BB];
        gp[tx * 2]     = add2(acc[i][0], bpr);
        gp[tx * 2 + 1] = add2(acc[i][1], bpr);
    }
}

__device__ void steal_loop(int tid, char* smraw,
                           const float* __restrict__ W, const float* __restrict__ bias) {
    __shared__ int sTk;
    for (;;) {
        __syncthreads();
        if (tid == 0) sTk = (int)atomicAdd(&g_ticket, 1u);
        __syncthreads();
        int tk = sTk;
        if (tk >= TT * 16) break;
        int t = tk >> 4, rt = tk & 15;
        if (tid == 0) {
            unsigned need = 2u * t + 2u;
            while (g_gen < need) { }
            __threadfence();
        }
        __syncthreads();
        gemm_unit(t, rt, tid, smraw, W, bias);
    }
}

// ---------------- fused kernel A: scan1 + gemm workers (1024 threads) ----------------
__global__ __launch_bounds__(NTS, 1)
void scanA_kernel(const float* __restrict__ sent,
                  const float* __restrict__ W_ih, const float* __restrict__ W_hh,
                  const float* __restrict__ b_cell,
                  const float* __restrict__ W1, const float* __restrict__ b1,
                  const float* __restrict__ W_ihl, const float* __restrict__ b_l) {
    extern __shared__ __align__(16) char smraw[];
    int tid = threadIdx.x;

    if (blockIdx.x < NB) {
        ull*   wS2  = (ull*)smraw;                    // [XDP][16] pairs {w,w}
        float* xS   = (float*)(wS2 + 16 * XDP);       // 2 x [128k][128b] double buffer
        float* gS   = xS + 2 * 16384;                 // [16][128]
        float* hb   = gS + 16 * BB;                   // 512
        float* ipS  = hb + HH;                        // 32
        float* pS   = ipS + 32;                       // 32
        float* phiS = pS + 32;                        // 64
        ull*   part = (ull*)xS;                       // aliases both buffers (128KB)

        int b   = blockIdx.x;
        int hu0 = b * 4;
        int bg = tid & 7, rg = (tid >> 3) & 7, kc = tid >> 6;   // kc 0..15
        int lane = tid & 31, wid = tid >> 5;
        int rot = b & 3;

        // permuted weights: k<512 -> W_hh col k; k>=512 -> W_ih col (k-512); k=575 pad 0
        for (int i = tid; i < 16 * XDP; i += NTS) {
            int k = i >> 4, r = i & 15;
            int g4 = r & 3, hl = r >> 2;
            int grow = g4 * HH + hu0 + hl;
            float w;
            if (k < HH) w = W_hh[grow * HH + k];
            else { int j = k - HH; w = (j < XD1) ? W_ih[grow * XD1 + j] : 0.0f; }
            wS2[i] = pk2(w, w);
        }
        int prow = tid >> 6;    // 0..15 output row
        int bp = tid & 63;      // batch pair
        float bias0 = b_cell[(prow & 3) * HH + hu0 + (prow >> 2)];
        ull bpr0 = pk2(bias0, bias0);
        __syncthreads();

        for (int t = 0; t < TT; t++) {
            const float* h1rd  = g_h1T[t & 1];
            const float* xwsrc = g_xw + t * 8192;

            // ---- phase A: attention window for batch b ----
            if (tid < HH) hb[tid] = __ldcg(g_h1 + b * HH + tid);
            __syncthreads();
            if (wid < 3 * KK) {
                int j = wid;
                float s = 0.0f;
                const float* w1r = W1 + j * HH;
                #pragma unroll
                for (int m = 0; m < 16; m++) {
                    int id = lane + 32 * m;
                    s += hb[id] * w1r[id];
                }
                for (int o = 16; o > 0; o >>= 1) s += __shfl_down_sync(0xffffffffu, s, o);
                if (lane == 0) ipS[j] = expf(s + b1[j]);
            }
            __syncthreads();
            if (tid < 3 * KK) {
                float pn = ipS[tid];
                if (tid >= 2 * KK) pn -= g_p[b * 3 * KK + tid];
                g_p[b * 3 * KK + tid] = pn;
                pS[tid] = pn;
            }
            __syncthreads();
            if (tid < SS) {
                float u = (float)(tid + 1);
                float s = 0.0f;
                #pragma unroll
                for (int k = 0; k < KK; k++) {
                    float d = pS[2 * KK + k] - u;
                    s += pS[k] * expf(-pS[KK + k] * d * d);
                }
                phiS[tid] = s;
            }
            __syncthreads();
            if (tid < CSLN) {
                float s = 0.0f;
                const float* sb = sent + b * SS * CSLN + tid;
                #pragma unroll 8
                for (int ss = 0; ss < SS; ss++) s += phiS[ss] * sb[ss * CSLN];
                g_xw[(t * 64 + DIN + tid) * BB + b] = s;
            }

            // preload h tile 0 while waiting at the barrier (valid since last step)
            float4 pf[4];
            {
                const float* s0 = h1rd + rot * 16384;
                #pragma unroll
                for (int q = 0; q < 4; q++)
                    pf[q] = __ldcg((const float4*)(s0 + q * 4096 + tid * 4));
            }
            gbar(2u * t + 1u);

            // ---- phase B: 4 x 128-k h tiles + 1 x 64-k xw tile ----
            ull acc[2][8];
            #pragma unroll
            for (int r = 0; r < 2; r++)
                #pragma unroll
                for (int j = 0; j < 8; j++) acc[r][j] = 0ull;

            for (int i = 0; i < 4; i++) {
                float* bufc = xS + (i & 1) * 16384;
                #pragma unroll
                for (int q = 0; q < 4; q++)
                    *(float4*)(bufc + q * 4096 + tid * 4) = pf[q];
                if (i < 3) {
                    const float* sn = h1rd + (((i + 1 + rot) & 3) * 16384);
                    #pragma unroll
                    for (int q = 0; q < 4; q++)
                        pf[q] = __ldcg((const float4*)(sn + q * 4096 + tid * 4));
                } else {
                    #pragma unroll
                    for (int q = 0; q < 2; q++)
                        pf[q] = __ldcg((const float4*)(xwsrc + q * 4096 + tid * 4));
                }
                __syncthreads();
                int kb = ((i + rot) & 3) * 128;
                #pragma unroll 4
                for (int kq = 0; kq < 8; kq++) {
                    int kk = kc * 8 + kq;
                    ulonglong2 wv = *(const ulonglong2*)&wS2[(kb + kk) * 16 + rg * 2];
                    ulonglong2 xa = *(const ulonglong2*)&bufc[kk * 128 + bg * 4];
                    ulonglong2 xb = *(const ulonglong2*)&bufc[kk * 128 + 32 + bg * 4];
                    ulonglong2 xc = *(const ulonglong2*)&bufc[kk * 128 + 64 + bg * 4];
                    ulonglong2 xd = *(const ulonglong2*)&bufc[kk * 128 + 96 + bg * 4];
                    acc[0][0] = fma2(wv.x, xa.x, acc[0][0]);
                    acc[0][1] = fma2(wv.x, xa.y, acc[0][1]);
                    acc[0][2] = fma2(wv.x, xb.x, acc[0][2]);
                    acc[0][3] = fma2(wv.x, xb.y, acc[0][3]);
                    acc[0][4] = fma2(wv.x, xc.x, acc[0][4]);
                    acc[0][5] = fma2(wv.x, xc.y, acc[0][5]);
                    acc[0][6] = fma2(wv.x, xd.x, acc[0][6]);
                    acc[0][7] = fma2(wv.x, xd.y, acc[0][7]);
                    acc[1][0] = fma2(wv.y, xa.x, acc[1][0]);
                    acc[1][1] = fma2(wv.y, xa.y, acc[1][1]);
                    acc[1][2] = fma2(wv.y, xb.x, acc[1][2]);
                    acc[1][3] = fma2(wv.y, xb.y, acc[1][3]);
                    acc[1][4] = fma2(wv.y, xc.x, acc[1][4]);
                    acc[1][5] = fma2(wv.y, xc.y, acc[1][5]);
                    acc[1][6] = fma2(wv.y, xd.x, acc[1][6]);
                    acc[1][7] = fma2(wv.y, xd.y, acc[1][7]);
                }
            }
            {   // last tile: 64 k rows of xw, buffer 0
                float* bufc = xS;
                #pragma unroll
                for (int q = 0; q < 2; q++)
                    *(float4*)(bufc + q * 4096 + tid * 4) = pf[q];
                __syncthreads();
                #pragma unroll 4
                for (int kq = 0; kq < 4; kq++) {
                    int kk = kc * 4 + kq;
                    ulonglong2 wv = *(const ulonglong2*)&wS2[(HH + kk) * 16 + rg * 2];
                    ulonglong2 xa = *(const ulonglong2*)&bufc[kk * 128 + bg * 4];
                    ulonglong2 xb = *(const ulonglong2*)&bufc[kk * 128 + 32 + bg * 4];
                    ulonglong2 xc = *(const ulonglong2*)&bufc[kk * 128 + 64 + bg * 4];
                    ulonglong2 xd = *(const ulonglong2*)&bufc[kk * 128 + 96 + bg * 4];
                    acc[0][0] = fma2(wv.x, xa.x, acc[0][0]);
                    acc[0][1] = fma2(wv.x, xa.y, acc[0][1]);
                    acc[0][2] = fma2(wv.x, xb.x, acc[0][2]);
                    acc[0][3] = fma2(wv.x, xb.y, acc[0][3]);
                    acc[0][4] = fma2(wv.x, xc.x, acc[0][4]);
                    acc[0][5] = fma2(wv.x, xc.y, acc[0][5]);
                    acc[0][6] = fma2(wv.x, xd.x, acc[0][6]);
                    acc[0][7] = fma2(wv.x, xd.y, acc[0][7]);
                    acc[1][0] = fma2(wv.y, xa.x, acc[1][0]);
                    acc[1][1] = fma2(wv.y, xa.y, acc[1][1]);
                    acc[1][2] = fma2(wv.y, xb.x, acc[1][2]);
                    acc[1][3] = fma2(wv.y, xb.y, acc[1][3]);
                    acc[1][4] = fma2(wv.y, xc.x, acc[1][4]);
                    acc[1][5] = fma2(wv.y, xc.y, acc[1][5]);
                    acc[1][6] = fma2(wv.y, xd.x, acc[1][6]);
                    acc[1][7] = fma2(wv.y, xd.y, acc[1][7]);
                }
            }
            __syncthreads();   // all compute done before partials overwrite buffers
            #pragma unroll
            for (int r = 0; r < 2; r++)
                #pragma unroll
                for (int j = 0; j < 8; j++)
                    part[(kc * 16 + rg * 2 + r) * 64 + (j >> 1) * 16 + bg * 2 + (j & 1)] = acc[r][j];
            __syncthreads();
            {
                ull s0 = bpr0;
                #pragma unroll
                for (int q = 0; q < 16; q++)
                    s0 = add2(s0, part[(q * 16 + prow) * 64 + bp]);
                ((ull*)gS)[prow * 64 + bp] = s0;
            }
            __syncthreads();
            if (tid < 4 * BB) {
                float* h1wr = g_h1T[(t + 1) & 1];
                int hl = tid >> 7, bb2 = tid & 127;
                int hu = hu0 + hl;
                float gi = sigf(gS[(hl * 4 + 0) * BB + bb2]);
                float gf = sigf(gS[(hl * 4 + 1) * BB + bb2]);
                float gg = tanhf(gS[(hl * 4 + 2) * BB + bb2]);
                float go = sigf(gS[(hl * 4 + 3) * BB + bb2]);
                float c = gf * g_c1T[hu * BB + bb2] + gi * gg;
                float h = go * tanhf(c);
                g_c1T[hu * BB + bb2] = c;
                h1wr[hu * BB + bb2] = h;
                g_h1[bb2 * HH + hu] = h;
                g_h1seqT[(t * HH + hu) * BB + bb2] = h;
            }
            gbar(2u * t + 2u);
        }
    }
    steal_loop(tid, smraw, W_ihl, b_l);
}

// ---------------- scan 2: second LSTM (1024 threads) ----------------
__global__ __launch_bounds__(NTS, 1)
void scan2_kernel(const float* __restrict__ W_hh_l) {
    extern __shared__ __align__(16) char smraw[];
    ull*   wS2 = (ull*)smraw;              // [512][16] pairs
    float* xS  = (float*)(wS2 + 16 * HH);  // 2 x [128k][128b] double buffer
    float* gS  = xS + 2 * 16384;           // [16][128]
    ull*   part = (ull*)xS;                // aliases both buffers

    int tid = threadIdx.x;
    int hu0 = blockIdx.x * 4;
    int bg = tid & 7, rg = (tid >> 3) & 7, kc = tid >> 6;   // kc 0..15
    int rot = blockIdx.x & 3;

    for (int i = tid; i < 16 * HH; i += NTS) {
        int k = i >> 4, r = i & 15;
        int g4 = r & 3, hl = r >> 2;
        float w = W_hh_l[(g4 * HH + hu0 + hl) * HH + k];
        wS2[i] = pk2(w, w);
    }
    int prow = tid >> 6;
    int bp = tid & 63;
    int grow = (prow & 3) * HH + hu0 + (prow >> 2);
    __syncthreads();

    for (int t = 0; t < TT; t++) {
        const float* hrd = g_h2T[t & 1];
        ull acc[2][8];
        #pragma unroll
        for (int r = 0; r < 2; r++)
            #pragma unroll
            for (int j = 0; j < 8; j++) acc[r][j] = 0ull;

        float4 pf[4];
        {
            const float* s0 = hrd + rot * 16384;
            #pragma unroll
            for (int q = 0; q < 4; q++)
                pf[q] = __ldcg((const float4*)(s0 + q * 4096 + tid * 4));
        }
        for (int i = 0; i < 4; i++) {
            float* bufc = xS + (i & 1) * 16384;
            #pragma unroll
            for (int q = 0; q < 4; q++)
                *(float4*)(bufc + q * 4096 + tid * 4) = pf[q];
            if (i < 3) {
                const float* sn = hrd + (((i + 1 + rot) & 3) * 16384);
                #pragma unroll
                for (int q = 0; q < 4; q++)
                    pf[q] = __ldcg((const float4*)(sn + q * 4096 + tid * 4));
            }
            __syncthreads();
            int kb = ((i + rot) & 3) * 128;
            #pragma unroll 4
            for (int kq = 0; kq < 8; kq++) {
                int kk = kc * 8 + kq;
                ulonglong2 wv = *(const ulonglong2*)&wS2[(kb + kk) * 16 + rg * 2];
                ulonglong2 xa = *(const ulonglong2*)&bufc[kk * 128 + bg * 4];
                ulonglong2 xb = *(const ulonglong2*)&bufc[kk * 128 + 32 + bg * 4];
                ulonglong2 xc = *(const ulonglong2*)&bufc[kk * 128 + 64 + bg * 4];
                ulonglong2 xd = *(const ulonglong2*)&bufc[kk * 128 + 96 + bg * 4];
                acc[0][0] = fma2(wv.x, xa.x, acc[0][0]);
                acc[0][1] = fma2(wv.x, xa.y, acc[0][1]);
                acc[0][2] = fma2(wv.x, xb.x, acc[0][2]);
                acc[0][3] = fma2(wv.x, xb.y, acc[0][3]);
                acc[0][4] = fma2(wv.x, xc.x, acc[0][4]);
                acc[0][5] = fma2(wv.x, xc.y, acc[0][5]);
                acc[0][6] = fma2(wv.x, xd.x, acc[0][6]);
                acc[0][7] = fma2(wv.x, xd.y, acc[0][7]);
                acc[1][0] = fma2(wv.y, xa.x, acc[1][0]);
                acc[1][1] = fma2(wv.y, xa.y, acc[1][1]);
                acc[1][2] = fma2(wv.y, xb.x, acc[1][2]);
                acc[1][3] = fma2(wv.y, xb.y, acc[1][3]);
                acc[1][4] = fma2(wv.y, xc.x, acc[1][4]);
                acc[1][5] = fma2(wv.y, xc.y, acc[1][5]);
                acc[1][6] = fma2(wv.y, xd.x, acc[1][6]);
                acc[1][7] = fma2(wv.y, xd.y, acc[1][7]);
            }
        }
        __syncthreads();
        #pragma unroll
        for (int r = 0; r < 2; r++)
            #pragma unroll
            for (int j = 0; j < 8; j++)
                part[(kc * 16 + rg * 2 + r) * 64 + (j >> 1) * 16 + bg * 2 + (j & 1)] = acc[r][j];
        __syncthreads();
        {
            const ull* pre = (const ull*)&g_gates2[(size_t)(t * G4H + grow) * BB];
            ull s0 = pre[bp];
            #pragma unroll
            for (int q = 0; q < 16; q++)
                s0 = add2(s0, part[(q * 16 + prow) * 64 + bp]);
            ((ull*)gS)[prow * 64 + bp] = s0;
        }
        __syncthreads();
        if (tid < 4 * BB) {
            float* hwr = g_h2T[(t + 1) & 1];
            int hl = tid >> 7, bb2 = tid & 127;
            int hu = hu0 + hl;
            float gi = sigf(gS[(hl * 4 + 0) * BB + bb2]);
            float gf = sigf(gS[(hl * 4 + 1) * BB + bb2]);
            float gg = tanhf(gS[(hl * 4 + 2) * BB + bb2]);
            float go = sigf(gS[(hl * 4 + 3) * BB + bb2]);
            float c = gf * g_c2T[hu * BB + bb2] + gi * gg;
            float h = go * tanhf(c);
            g_c2T[hu * BB + bb2] = c;
            hwr[hu * BB + bb2] = h;
            g_yT[(t * HH + hu) * BB + bb2] = h;
        }
        gbar(512u + t + 1u);
    }
}

// ---------------- final projection ----------------
__global__ void final_kernel(const float* __restrict__ W2, const float* __restrict__ b2,
                             float* __restrict__ out) {
    __shared__ float w_s[128 * 33];
    __shared__ float y_s[32 * 128];
    int t = blockIdx.x;
    int tid = threadIdx.x, tx = tid & 15, ty = tid >> 4;
    int lk = tid & 31, lo0 = tid >> 5;
    int lb = tid & 127, lq = tid >> 7;

    float acc[8][8];
    #pragma unroll
    for (int i = 0; i < 8; i++)
        #pragma unroll
        for (int j = 0; j < 8; j++) acc[i][j] = 0.0f;

    for (int k0 = 0; k0 < HH; k0 += 32) {
        for (int oo = lo0; oo < 128; oo += 8)
            w_s[oo * 33 + lk] = (oo < DOUT) ? W2[oo * HH + k0 + lk] : 0.0f;
        for (int kk = lq; kk < 32; kk += 2)
            y_s[kk * BB + lb] = g_yT[(t * HH + k0 + kk) * BB + lb];
        __syncthreads();
        for (int kk = 0; kk < 32; kk++) {
            float wf[8];
            #pragma unroll
            for (int i = 0; i < 8; i++) wf[i] = w_s[(ty * 8 + i) * 33 + kk];
            float4 xa = *(const float4*)&y_s[kk * 128 + tx * 4];
            float4 xb = *(const float4*)&y_s[kk * 128 + 64 + tx * 4];
            float xf[8] = {xa.x, xa.y, xa.z, xa.w, xb.x, xb.y, xb.z, xb.w};
            #pragma unroll
            for (int i = 0; i < 8; i++)
                #pragma unroll
                for (int j = 0; j < 8; j++) acc[i][j] += wf[i] * xf[j];
        }
        __syncthreads();
    }
    #pragma unroll
    for (int i = 0; i < 8; i++) {
        int o = ty * 8 + i;
        if (o < DOUT) {
            float bi = b2[o];
            #pragma unroll
            for (int j = 0; j < 8; j++) {
                int bb2 = (j >> 2) * 64 + tx * 4 + (j & 3);
                out[(size_t)(bb2 * TT + t) * DOUT + o] = acc[i][j] + bi;
            }
        }
    }
}

// ---------------- epilogue ----------------
__global__ void epi_kernel(float* __restrict__ out) {
    int idx = blockIdx.x * blockDim.x + threadIdx.x;
    if (idx >= BB * HH) return;
    int b = idx / HH, h = idx % HH;
    size_t base = (size_t)BB * TT * DOUT;
    out[base + idx]               = g_h1[idx];
    out[base + BB * HH + idx]     = g_c1T[h * BB + b];
    out[base + 2 * BB * HH + idx] = g_h2T[0][h * BB + b];
    out[base + 3 * BB * HH + idx] = g_c2T[h * BB + b];
}

extern "C" void kernel_launch(void* const* d_in, const int* in_sizes, int n_in,
                              void* d_out, int out_size) {
    const float* x      = (const float*)d_in[0];
    const float* sent   = (const float*)d_in[1];
    const float* h1h    = (const float*)d_in[2];
    const float* h1c    = (const float*)d_in[3];
    const float* h2h    = (const float*)d_in[4];
    const float* h2c    = (const float*)d_in[5];
    const float* Wihc   = (const float*)d_in[6];
    const float* Whhc   = (const float*)d_in[7];
    const float* bcell  = (const float*)d_in[8];
    const float* Wihl   = (const float*)d_in[9];
    const float* Whhl   = (const float*)d_in[10];
    const float* bl     = (const float*)d_in[11];
    const float* W1     = (const float*)d_in[12];
    const float* b1     = (const float*)d_in[13];
    const float* W2     = (const float*)d_in[14];
    const float* b2     = (const float*)d_in[15];
    float* out = (float*)d_out;

    // scanA: wS2 73728 + xS 131072 + gS 8192 + hb 2048 + misc 512 = 215552 B
    size_t smA = (size_t)16 * XDP * 8 + 2 * 16384 * 4 + 16 * BB * 4 + HH * 4 + 128 * 4;
    // scan2: wS2 65536 + xS 131072 + gS 8192 = 204800 B
    size_t sm2 = (size_t)16 * HH * 8 + 2 * 16384 * 4 + 16 * BB * 4;
    cudaFuncSetAttribute(scanA_kernel, cudaFuncAttributeMaxDynamicSharedMemorySize, (int)smA);
    cudaFuncSetAttribute(scan2_kernel, cudaFuncAttributeMaxDynamicSharedMemorySize, (int)sm2);

    int init_n = BB * HH + BB * 3 * KK + TT * DIN * BB + TT * BB;
    init_kernel<<<(init_n + 255) / 256, 256>>>(x, h1h, h1c, h2h, h2c);
    scanA_kernel<<<NBA, NTS, smA>>>(sent, Wihc, Whhc, bcell, W1, b1, Wihl, bl);
    scan2_kernel<<<NB, NTS, sm2>>>(Whhl);
    final_kernel<<<TT, 256>>>(W2, b2, out);
    epi_kernel<<<(BB * HH + 255) / 256, 256>>>(out);
}

// round 13
// speedup vs baseline: 1.1417x; 1.1417x over previous
#include <cuda_runtime.h>
#include <cuda_bf16.h>
#include <math.h>

#define BB   128
#define TT   256
#define SS   64
#define DIN  3
#define HH   512
#define KK   10
#define CSLN 60
#define DOUT 121
#define G4H  2048
#define XD   575   // DIN + CSLN + HH (gemm order: x,win,h)
#define XD1  63    // DIN + CSLN
#define XDP  576   // scan1 permuted+padded: [h 512 | x 3 | win 60 | zero 1]

#define NB   128   // scan blocks (barrier count)
#define NBA  148   // total blocks in fused kernel (all resident)
#define NTS  512

typedef unsigned long long ull;

__device__ __forceinline__ ull pk2(float lo, float hi) {
    ull r; asm("mov.b64 %0,{%1,%2};" : "=l"(r) : "f"(lo), "f"(hi)); return r;
}
__device__ __forceinline__ ull fma2(ull a, ull b, ull c) {
    ull d; asm("fma.rn.f32x2 %0,%1,%2,%3;" : "=l"(d) : "l"(a), "l"(b), "l"(c)); return d;
}
__device__ __forceinline__ ull add2(ull a, ull b) {
    ull d; asm("add.rn.f32x2 %0,%1,%2;" : "=l"(d) : "l"(a), "l"(b)); return d;
}

// 32 FFMA2 micro-tile: 4 rows x 8 batch-pairs
#define MMA32(wv0, wv1, xa, xb, xc, xd)                 \
    acc[0][0] = fma2(wv0.x, xa.x, acc[0][0]);           \
    acc[0][1] = fma2(wv0.x, xa.y, acc[0][1]);           \
    acc[0][2] = fma2(wv0.x, xb.x, acc[0][2]);           \
    acc[0][3] = fma2(wv0.x, xb.y, acc[0][3]);           \
    acc[0][4] = fma2(wv0.x, xc.x, acc[0][4]);           \
    acc[0][5] = fma2(wv0.x, xc.y, acc[0][5]);           \
    acc[0][6] = fma2(wv0.x, xd.x, acc[0][6]);           \
    acc[0][7] = fma2(wv0.x, xd.y, acc[0][7]);           \
    acc[1][0] = fma2(wv0.y, xa.x, acc[1][0]);           \
    acc[1][1] = fma2(wv0.y, xa.y, acc[1][1]);           \
    acc[1][2] = fma2(wv0.y, xb.x, acc[1][2]);           \
    acc[1][3] = fma2(wv0.y, xb.y, acc[1][3]);           \
    acc[1][4] = fma2(wv0.y, xc.x, acc[1][4]);           \
    acc[1][5] = fma2(wv0.y, xc.y, acc[1][5]);           \
    acc[1][6] = fma2(wv0.y, xd.x, acc[1][6]);           \
    acc[1][7] = fma2(wv0.y, xd.y, acc[1][7]);           \
    acc[2][0] = fma2(wv1.x, xa.x, acc[2][0]);           \
    acc[2][1] = fma2(wv1.x, xa.y, acc[2][1]);           \
    acc[2][2] = fma2(wv1.x, xb.x, acc[2][2]);           \
    acc[2][3] = fma2(wv1.x, xb.y, acc[2][3]);           \
    acc[2][4] = fma2(wv1.x, xc.x, acc[2][4]);           \
    acc[2][5] = fma2(wv1.x, xc.y, acc[2][5]);           \
    acc[2][6] = fma2(wv1.x, xd.x, acc[2][6]);           \
    acc[2][7] = fma2(wv1.x, xd.y, acc[2][7]);           \
    acc[3][0] = fma2(wv1.y, xa.x, acc[3][0]);           \
    acc[3][1] = fma2(wv1.y, xa.y, acc[3][1]);           \
    acc[3][2] = fma2(wv1.y, xb.x, acc[3][2]);           \
    acc[3][3] = fma2(wv1.y, xb.y, acc[3][3]);           \
    acc[3][4] = fma2(wv1.y, xc.x, acc[3][4]);           \
    acc[3][5] = fma2(wv1.y, xc.y, acc[3][5]);           \
    acc[3][6] = fma2(wv1.y, xd.x, acc[3][6]);           \
    acc[3][7] = fma2(wv1.y, xd.y, acc[3][7]);

// ---------------- device scratch ----------------
__device__ __align__(16) float g_h1[BB * HH];
__device__ __align__(16) float g_h1T[2][HH * BB];
__device__ __align__(16) float g_c1T[HH * BB];
__device__ __align__(16) float g_h2T[2][HH * BB];
__device__ __align__(16) float g_c2T[HH * BB];
__device__ __align__(16) float g_p[BB * 3 * KK];
__device__ __align__(16) float g_xw[TT * 64 * BB];   // [t][64: x0..2,win0..59,zero][b]
__device__ __align__(16) float g_h1seqT[TT * HH * BB];
__device__ __align__(16) float g_gates2[TT * G4H * BB];
__device__ __align__(16) float g_yT[TT * HH * BB];
__device__ volatile unsigned g_gen = 0;
__device__ volatile unsigned g_flag[NB * 32];   // padded: one flag per 128B
__device__ unsigned g_ticket = 0;

__device__ __forceinline__ float sigf(float x) { return 1.0f / (1.0f + expf(-x)); }

// flag barrier across the NB scan blocks; target is a monotone generation number
__device__ __forceinline__ void gbar(unsigned target) {
    __syncthreads();
    int tid = threadIdx.x;
    if (blockIdx.x == 0) {
        if (tid == 0) __threadfence();
        if (tid >= 1 && tid < NB) {
            while (g_flag[tid * 32] < target) { }
        }
        __syncthreads();
        if (tid == 0) { __threadfence(); g_gen = target; }
    } else {
        if (tid == 0) {
            __threadfence();
            g_flag[blockIdx.x * 32] = target;
            while (g_gen < target) { }
        }
        __syncthreads();
    }
}

// ---------------- init ----------------
__global__ void init_kernel(const float* __restrict__ x,
                            const float* __restrict__ h1h, const float* __restrict__ h1c,
                            const float* __restrict__ h2h, const float* __restrict__ h2c) {
    int idx = blockIdx.x * blockDim.x + threadIdx.x;
    if (idx == 0) { g_gen = 0; g_ticket = 0; }
    if (idx < NB * 32) g_flag[idx] = 0;
    if (idx < BB * HH) {
        int b = idx / HH, h = idx % HH;
        float v = h1h[idx];
        g_h1[idx] = v;
        g_h1T[0][h * BB + b] = v;
        g_c1T[h * BB + b] = h1c[idx];
        g_h2T[0][h * BB + b] = h2h[idx];
        g_c2T[h * BB + b] = h2c[idx];
    }
    int i2 = idx - BB * HH;
    if (i2 >= 0 && i2 < BB * 3 * KK) g_p[i2] = 0.0f;
    int i3 = idx - BB * HH - BB * 3 * KK;
    if (i3 >= 0 && i3 < TT * DIN * BB) {
        int b = i3 % BB;
        int r = i3 / BB;
        int t = r / DIN, i = r % DIN;
        g_xw[(t * 64 + i) * BB + b] = x[(b * TT + t) * DIN + i];
    }
    int i4 = i3 - TT * DIN * BB;
    if (i4 >= 0 && i4 < TT * BB) {
        int t = i4 / BB, b = i4 % BB;
        g_xw[(t * 64 + 63) * BB + b] = 0.0f;
    }
}

// gemm feature fetch (original order): kg in [0,XD)
__device__ __forceinline__ float fetch_seq(int t, int kg, int bb) {
    if (kg < XD1) return g_xw[(t * 64 + kg) * BB + bb];
    else          return g_h1seqT[(t * HH + (kg - XD1)) * BB + bb];
}

// ---------------- gemm work unit: gates2[t] rows [rt*128, rt*128+128) ----------------
__device__ void gemm_unit(int t, int rt, int tid, char* smraw,
                          const float* __restrict__ W, const float* __restrict__ bias) {
    ull*   a_s = (ull*)smraw;               // [128][33] pairs {w,w}
    float* x_s = (float*)(a_s + 128 * 33);  // [32][128]
    int ty = tid >> 5, tx = tid & 31;

    ull acc[8][2];
    #pragma unroll
    for (int i = 0; i < 8; i++) { acc[i][0] = 0ull; acc[i][1] = 0ull; }

    for (int k0 = 0; k0 < XD; k0 += 32) {
        for (int i = tid; i < 128 * 32; i += NTS) {
            int row = i >> 5, kk = i & 31;
            int k = k0 + kk;
            float w = (k < XD) ? W[(rt * 128 + row) * XD + k] : 0.0f;
            a_s[row * 33 + kk] = pk2(w, w);
        }
        for (int i = tid; i < 32 * 128; i += NTS) {
            int kk = i >> 7, bb = i & 127;
            int k = k0 + kk;
            x_s[i] = (k < XD) ? fetch_seq(t, k, bb) : 0.0f;
        }
        __syncthreads();
        #pragma unroll 4
        for (int kk = 0; kk < 32; kk++) {
            ulonglong2 xv = *(const ulonglong2*)&x_s[kk * 128 + tx * 4];
            #pragma unroll
            for (int i = 0; i < 8; i++) {
                ull w2 = a_s[(ty * 8 + i) * 33 + kk];
                acc[i][0] = fma2(w2, xv.x, acc[i][0]);
                acc[i][1] = fma2(w2, xv.y, acc[i][1]);
            }
        }
        __syncthreads();
    }
    #pragma unroll
    for (int i = 0; i < 8; i++) {
        int row = rt * 128 + ty * 8 + i;
        float bi = bias[row];
        ull bpr = pk2(bi, bi);
        ull* gp = (ull*)&g_gates2[(size_t)(t * G4H + row) * BB];
        gp[tx * 2]     = add2(acc[i][0], bpr);
        gp[tx * 2 + 1] = add2(acc[i][1], bpr);
    }
}

__device__ void steal_loop(int tid, char* smraw,
                           const float* __restrict__ W, const float* __restrict__ bias) {
    __shared__ int sTk;
    for (;;) {
        __syncthreads();
        if (tid == 0) sTk = (int)atomicAdd(&g_ticket, 1u);
        __syncthreads();
        int tk = sTk;
        if (tk >= TT * 16) break;
        int t = tk >> 4, rt = tk & 15;
        if (tid == 0) {
            unsigned need = 2u * t + 2u;
            while (g_gen < need) { }
            __threadfence();
        }
        __syncthreads();
        gemm_unit(t, rt, tid, smraw, W, bias);
    }
}

// ---------------- fused kernel A: scan1 + gemm workers ----------------
__global__ __launch_bounds__(NTS, 1)
void scanA_kernel(const float* __restrict__ sent,
                  const float* __restrict__ W_ih, const float* __restrict__ W_hh,
                  const float* __restrict__ b_cell,
                  const float* __restrict__ W1, const float* __restrict__ b1,
                  const float* __restrict__ W_ihl, const float* __restrict__ b_l) {
    extern __shared__ __align__(16) char smraw[];
    int tid = threadIdx.x;

    if (blockIdx.x < NB) {
        ull*   wS2  = (ull*)smraw;                    // [XDP][16] pairs {w,w}
        float* xS   = (float*)(wS2 + 16 * XDP);       // 2 x [128k][128b] double buffer
        float* gS   = xS + 2 * 16384;                 // [16][128]
        float* hb   = gS + 16 * BB;                   // 512
        float* ipS  = hb + HH;                        // 32
        float* pS   = ipS + 32;                       // 32
        float* phiS = pS + 32;                        // 64
        ull*   part = (ull*)xS;                       // aliases BOTH buffers (128KB)

        int b   = blockIdx.x;
        int hu0 = b * 4;
        int bg = tid & 7, rg = (tid >> 3) & 3, kc = tid >> 5;   // kc 0..15
        int lane = tid & 31, wid = tid >> 5;
        int rot = b & 3;

        // permuted weights: k<512 -> W_hh col k; k>=512 -> W_ih col (k-512); k=575 pad 0
        for (int i = tid; i < 16 * XDP; i += NTS) {
            int k = i >> 4, r = i & 15;
            int g4 = r & 3, hl = r >> 2;
            int grow = g4 * HH + hu0 + hl;
            float w;
            if (k < HH) w = W_hh[grow * HH + k];
            else { int j = k - HH; w = (j < XD1) ? W_ih[grow * XD1 + j] : 0.0f; }
            wS2[i] = pk2(w, w);
        }
        int prow0 = tid >> 6, prow1 = prow0 + 8;
        int bp = tid & 63;
        float bias0 = b_cell[(prow0 & 3) * HH + hu0 + (prow0 >> 2)];
        float bias1 = b_cell[(prow1 & 3) * HH + hu0 + (prow1 >> 2)];
        ull bpr0 = pk2(bias0, bias0), bpr1 = pk2(bias1, bias1);
        __syncthreads();

        for (int t = 0; t < TT; t++) {
            const float* h1rd  = g_h1T[t & 1];
            const float* xwsrc = g_xw + t * 8192;

            // ---- phase A: attention window for batch b ----
            if (tid < HH) hb[tid] = __ldcg(g_h1 + b * HH + tid);
            __syncthreads();
            for (int j = wid; j < 3 * KK; j += 16) {
                float s = 0.0f;
                const float* w1r = W1 + j * HH;
                #pragma unroll
                for (int m = 0; m < 16; m++) {
                    int id = lane + 32 * m;
                    s += hb[id] * w1r[id];
                }
                for (int o = 16; o > 0; o >>= 1) s += __shfl_down_sync(0xffffffffu, s, o);
                if (lane == 0) ipS[j] = expf(s + b1[j]);
            }
            __syncthreads();
            if (tid < 3 * KK) {
                float pn = ipS[tid];
                if (tid >= 2 * KK) pn -= g_p[b * 3 * KK + tid];
                g_p[b * 3 * KK + tid] = pn;
                pS[tid] = pn;
            }
            __syncthreads();
            if (tid < SS) {
                float u = (float)(tid + 1);
                float s = 0.0f;
                #pragma unroll
                for (int k = 0; k < KK; k++) {
                    float d = pS[2 * KK + k] - u;
                    s += pS[k] * expf(-pS[KK + k] * d * d);
                }
                phiS[tid] = s;
            }
            __syncthreads();
            if (tid < CSLN) {
                float s = 0.0f;
                const float* sb = sent + b * SS * CSLN + tid;
                #pragma unroll 8
                for (int ss = 0; ss < SS; ss++) s += phiS[ss] * sb[ss * CSLN];
                g_xw[(t * 64 + DIN + tid) * BB + b] = s;
            }

            // preload h tile 0 while waiting at the barrier (valid since last step)
            float4 pf[8];
            {
                const float* s0 = h1rd + rot * 16384;
                #pragma unroll
                for (int q = 0; q < 8; q++)
                    pf[q] = __ldcg((const float4*)(s0 + q * 2048 + tid * 4));
            }
            gbar(2u * t + 1u);

            // ---- phase B: 4 x 128-k h tiles + 1 x 64-k xw tile ----
            ull acc[4][8];
            #pragma unroll
            for (int r = 0; r < 4; r++)
                #pragma unroll
                for (int j = 0; j < 8; j++) acc[r][j] = 0ull;

            for (int i = 0; i < 4; i++) {
                float* bufc = xS + (i & 1) * 16384;
                #pragma unroll
                for (int q = 0; q < 8; q++)
                    *(float4*)(bufc + q * 2048 + tid * 4) = pf[q];
                if (i < 3) {
                    const float* sn = h1rd + (((i + 1 + rot) & 3) * 16384);
                    #pragma unroll
                    for (int q = 0; q < 8; q++)
                        pf[q] = __ldcg((const float4*)(sn + q * 2048 + tid * 4));
                } else {
                    #pragma unroll
                    for (int q = 0; q < 4; q++)
                        pf[q] = __ldcg((const float4*)(xwsrc + q * 2048 + tid * 4));
                }
                __syncthreads();
                int kb = ((i + rot) & 3) * 128;
                #pragma unroll 4
                for (int kq = 0; kq < 8; kq++) {
                    int kk = kc * 8 + kq;
                    ulonglong2 wv0 = *(const ulonglong2*)&wS2[(kb + kk) * 16 + rg * 4];
                    ulonglong2 wv1 = *(const ulonglong2*)&wS2[(kb + kk) * 16 + rg * 4 + 2];
                    ulonglong2 xa = *(const ulonglong2*)&bufc[kk * 128 + bg * 4];
                    ulonglong2 xb = *(const ulonglong2*)&bufc[kk * 128 + 32 + bg * 4];
                    ulonglong2 xc = *(const ulonglong2*)&bufc[kk * 128 + 64 + bg * 4];
                    ulonglong2 xd = *(const ulonglong2*)&bufc[kk * 128 + 96 + bg * 4];
                    MMA32(wv0, wv1, xa, xb, xc, xd)
                }
            }
            {   // last tile: 64 k rows of xw, buffer 0
                float* bufc = xS;
                #pragma unroll
                for (int q = 0; q < 4; q++)
                    *(float4*)(bufc + q * 2048 + tid * 4) = pf[q];
                __syncthreads();
                #pragma unroll 4
                for (int kq = 0; kq < 4; kq++) {
                    int kk = kc * 4 + kq;
                    ulonglong2 wv0 = *(const ulonglong2*)&wS2[(HH + kk) * 16 + rg * 4];
                    ulonglong2 wv1 = *(const ulonglong2*)&wS2[(HH + kk) * 16 + rg * 4 + 2];
                    ulonglong2 xa = *(const ulonglong2*)&bufc[kk * 128 + bg * 4];
                    ulonglong2 xb = *(const ulonglong2*)&bufc[kk * 128 + 32 + bg * 4];
                    ulonglong2 xc = *(const ulonglong2*)&bufc[kk * 128 + 64 + bg * 4];
                    ulonglong2 xd = *(const ulonglong2*)&bufc[kk * 128 + 96 + bg * 4];
                    MMA32(wv0, wv1, xa, xb, xc, xd)
                }
            }
            __syncthreads();   // all compute done before partials overwrite buffers
            #pragma unroll
            for (int r = 0; r < 4; r++)
                #pragma unroll
                for (int j = 0; j < 8; j++)
                    part[(kc * 16 + rg * 4 + r) * 64 + (j >> 1) * 16 + bg * 2 + (j & 1)] = acc[r][j];
            __syncthreads();
            {
                ull s0 = bpr0, s1 = bpr1;
                #pragma unroll
                for (int q = 0; q < 16; q++) {
                    s0 = add2(s0, part[(q * 16 + prow0) * 64 + bp]);
                    s1 = add2(s1, part[(q * 16 + prow1) * 64 + bp]);
                }
                ((ull*)gS)[prow0 * 64 + bp] = s0;
                ((ull*)gS)[prow1 * 64 + bp] = s1;
            }
            __syncthreads();
            {
                float* h1wr = g_h1T[(t + 1) & 1];
                int hl = tid >> 7, bb2 = tid & 127;
                int hu = hu0 + hl;
                float gi = sigf(gS[(hl * 4 + 0) * BB + bb2]);
                float gf = sigf(gS[(hl * 4 + 1) * BB + bb2]);
                float gg = tanhf(gS[(hl * 4 + 2) * BB + bb2]);
                float go = sigf(gS[(hl * 4 + 3) * BB + bb2]);
                float c = gf * g_c1T[hu * BB + bb2] + gi * gg;
                float h = go * tanhf(c);
                g_c1T[hu * BB + bb2] = c;
                h1wr[hu * BB + bb2] = h;
                g_h1[bb2 * HH + hu] = h;
                g_h1seqT[(t * HH + hu) * BB + bb2] = h;
            }
            gbar(2u * t + 2u);
        }
    }
    steal_loop(tid, smraw, W_ihl, b_l);
}

// ---------------- scan 2: second LSTM ----------------
__global__ __launch_bounds__(NTS, 1)
void scan2_kernel(const float* __restrict__ W_hh_l) {
    extern __shared__ __align__(16) char smraw[];
    ull*   wS2 = (ull*)smraw;              // [512][16] pairs
    float* xS  = (float*)(wS2 + 16 * HH);  // 2 x [128k][128b] double buffer
    float* gS  = xS + 2 * 16384;           // [16][128]
    ull*   part = (ull*)xS;                // aliases BOTH buffers

    int tid = threadIdx.x;
    int hu0 = blockIdx.x * 4;
    int bg = tid & 7, rg = (tid >> 3) & 3, kc = tid >> 5;   // kc 0..15
    int rot = blockIdx.x & 3;

    for (int i = tid; i < 16 * HH; i += NTS) {
        int k = i >> 4, r = i & 15;
        int g4 = r & 3, hl = r >> 2;
        float w = W_hh_l[(g4 * HH + hu0 + hl) * HH + k];
        wS2[i] = pk2(w, w);
    }
    int prow0 = tid >> 6, prow1 = prow0 + 8;
    int bp = tid & 63;
    int grow0 = (prow0 & 3) * HH + hu0 + (prow0 >> 2);
    int grow1 = (prow1 & 3) * HH + hu0 + (prow1 >> 2);
    __syncthreads();

    for (int t = 0; t < TT; t++) {
        const float* hrd = g_h2T[t & 1];
        ull acc[4][8];
        #pragma unroll
        for (int r = 0; r < 4; r++)
            #pragma unroll
            for (int j = 0; j < 8; j++) acc[r][j] = 0ull;

        float4 pf[8];
        {
            const float* s0 = hrd + rot * 16384;
            #pragma unroll
            for (int q = 0; q < 8; q++)
                pf[q] = __ldcg((const float4*)(s0 + q * 2048 + tid * 4));
        }
        for (int i = 0; i < 4; i++) {
            float* bufc = xS + (i & 1) * 16384;
            #pragma unroll
            for (int q = 0; q < 8; q++)
                *(float4*)(bufc + q * 2048 + tid * 4) = pf[q];
            if (i < 3) {
                const float* sn = hrd + (((i + 1 + rot) & 3) * 16384);
                #pragma unroll
                for (int q = 0; q < 8; q++)
                    pf[q] = __ldcg((const float4*)(sn + q * 2048 + tid * 4));
            }
            __syncthreads();
            int kb = ((i + rot) & 3) * 128;
            #pragma unroll 4
            for (int kq = 0; kq < 8; kq++) {
                int kk = kc * 8 + kq;
                ulonglong2 wv0 = *(const ulonglong2*)&wS2[(kb + kk) * 16 + rg * 4];
                ulonglong2 wv1 = *(const ulonglong2*)&wS2[(kb + kk) * 16 + rg * 4 + 2];
                ulonglong2 xa = *(const ulonglong2*)&bufc[kk * 128 + bg * 4];
                ulonglong2 xb = *(const ulonglong2*)&bufc[kk * 128 + 32 + bg * 4];
                ulonglong2 xc = *(const ulonglong2*)&bufc[kk * 128 + 64 + bg * 4];
                ulonglong2 xd = *(const ulonglong2*)&bufc[kk * 128 + 96 + bg * 4];
                MMA32(wv0, wv1, xa, xb, xc, xd)
            }
        }
        __syncthreads();
        #pragma unroll
        for (int r = 0; r < 4; r++)
            #pragma unroll
            for (int j = 0; j < 8; j++)
                part[(kc * 16 + rg * 4 + r) * 64 + (j >> 1) * 16 + bg * 2 + (j & 1)] = acc[r][j];
        __syncthreads();
        {
            const ull* pre0 = (const ull*)&g_gates2[(size_t)(t * G4H + grow0) * BB];
            const ull* pre1 = (const ull*)&g_gates2[(size_t)(t * G4H + grow1) * BB];
            ull s0 = pre0[bp], s1 = pre1[bp];
            #pragma unroll
            for (int q = 0; q < 16; q++) {
                s0 = add2(s0, part[(q * 16 + prow0) * 64 + bp]);
                s1 = add2(s1, part[(q * 16 + prow1) * 64 + bp]);
            }
            ((ull*)gS)[prow0 * 64 + bp] = s0;
            ((ull*)gS)[prow1 * 64 + bp] = s1;
        }
        __syncthreads();
        {
            float* hwr = g_h2T[(t + 1) & 1];
            int hl = tid >> 7, bb2 = tid & 127;
            int hu = hu0 + hl;
            float gi = sigf(gS[(hl * 4 + 0) * BB + bb2]);
            float gf = sigf(gS[(hl * 4 + 1) * BB + bb2]);
            float gg = tanhf(gS[(hl * 4 + 2) * BB + bb2]);
            float go = sigf(gS[(hl * 4 + 3) * BB + bb2]);
            float c = gf * g_c2T[hu * BB + bb2] + gi * gg;
            float h = go * tanhf(c);
            g_c2T[hu * BB + bb2] = c;
            hwr[hu * BB + bb2] = h;
            g_yT[(t * HH + hu) * BB + bb2] = h;
        }
        gbar(512u + t + 1u);
    }
}

// ---------------- final projection ----------------
__global__ void final_kernel(const float* __restrict__ W2, const float* __restrict__ b2,
                             float* __restrict__ out) {
    __shared__ float w_s[128 * 33];
    __shared__ float y_s[32 * 128];
    int t = blockIdx.x;
    int tid = threadIdx.x, tx = tid & 15, ty = tid >> 4;
    int lk = tid & 31, lo0 = tid >> 5;
    int lb = tid & 127, lq = tid >> 7;

    float acc[8][8];
    #pragma unroll
    for (int i = 0; i < 8; i++)
        #pragma unroll
        for (int j = 0; j < 8; j++) acc[i][j] = 0.0f;

    for (int k0 = 0; k0 < HH; k0 += 32) {
        for (int oo = lo0; oo < 128; oo += 8)
            w_s[oo * 33 + lk] = (oo < DOUT) ? W2[oo * HH + k0 + lk] : 0.0f;
        for (int kk = lq; kk < 32; kk += 2)
            y_s[kk * BB + lb] = g_yT[(t * HH + k0 + kk) * BB + lb];
        __syncthreads();
        for (int kk = 0; kk < 32; kk++) {
            float wf[8];
            #pragma unroll
            for (int i = 0; i < 8; i++) wf[i] = w_s[(ty * 8 + i) * 33 + kk];
            float4 xa = *(const float4*)&y_s[kk * 128 + tx * 4];
            float4 xb = *(const float4*)&y_s[kk * 128 + 64 + tx * 4];
            float xf[8] = {xa.x, xa.y, xa.z, xa.w, xb.x, xb.y, xb.z, xb.w};
            #pragma unroll
            for (int i = 0; i < 8; i++)
                #pragma unroll
                for (int j = 0; j < 8; j++) acc[i][j] += wf[i] * xf[j];
        }
        __syncthreads();
    }
    #pragma unroll
    for (int i = 0; i < 8; i++) {
        int o = ty * 8 + i;
        if (o < DOUT) {
            float bi = b2[o];
            #pragma unroll
            for (int j = 0; j < 8; j++) {
                int bb2 = (j >> 2) * 64 + tx * 4 + (j & 3);
                out[(size_t)(bb2 * TT + t) * DOUT + o] = acc[i][j] + bi;
            }
        }
    }
}

// ---------------- epilogue ----------------
__global__ void epi_kernel(float* __restrict__ out) {
    int idx = blockIdx.x * blockDim.x + threadIdx.x;
    if (idx >= BB * HH) return;
    int b = idx / HH, h = idx % HH;
    size_t base = (size_t)BB * TT * DOUT;
    out[base + idx]               = g_h1[idx];
    out[base + BB * HH + idx]     = g_c1T[h * BB + b];
    out[base + 2 * BB * HH + idx] = g_h2T[0][h * BB + b];
    out[base + 3 * BB * HH + idx] = g_c2T[h * BB + b];
}

extern "C" void kernel_launch(void* const* d_in, const int* in_sizes, int n_in,
                              void* d_out, int out_size) {
    const float* x      = (const float*)d_in[0];
    const float* sent   = (const float*)d_in[1];
    const float* h1h    = (const float*)d_in[2];
    const float* h1c    = (const float*)d_in[3];
    const float* h2h    = (const float*)d_in[4];
    const float* h2c    = (const float*)d_in[5];
    const float* Wihc   = (const float*)d_in[6];
    const float* Whhc   = (const float*)d_in[7];
    const float* bcell  = (const float*)d_in[8];
    const float* Wihl   = (const float*)d_in[9];
    const float* Whhl   = (const float*)d_in[10];
    const float* bl     = (const float*)d_in[11];
    const float* W1     = (const float*)d_in[12];
    const float* b1     = (const float*)d_in[13];
    const float* W2     = (const float*)d_in[14];
    const float* b2     = (const float*)d_in[15];
    float* out = (float*)d_out;

    // scanA: wS2 73728 + xS 131072 + gS 8192 + hb 2048 + misc 512 = 215552 B
    size_t smA = (size_t)16 * XDP * 8 + 2 * 16384 * 4 + 16 * BB * 4 + HH * 4 + 128 * 4;
    // scan2: wS2 65536 + xS 131072 + gS 8192 = 204800 B
    size_t sm2 = (size_t)16 * HH * 8 + 2 * 16384 * 4 + 16 * BB * 4;
    cudaFuncSetAttribute(scanA_kernel, cudaFuncAttributeMaxDynamicSharedMemorySize, (int)smA);
    cudaFuncSetAttribute(scan2_kernel, cudaFuncAttributeMaxDynamicSharedMemorySize, (int)sm2);

    int init_n = BB * HH + BB * 3 * KK + TT * DIN * BB + TT * BB;
    init_kernel<<<(init_n + 255) / 256, 256>>>(x, h1h, h1c, h2h, h2c);
    scanA_kernel<<<NBA, NTS, smA>>>(sent, Wihc, Whhc, bcell, W1, b1, Wihl, bl);
    scan2_kernel<<<NB, NTS, sm2>>>(Whhl);
    final_kernel<<<TT, 256>>>(W2, b2, out);
    epi_kernel<<<(BB * HH + 255) / 256, 256>>>(out);
}